// round 17
// baseline (speedup 1.0000x reference)
#include <cuda_runtime.h>
#include <cuda_bf16.h>
#include <cstdint>

#define NB    1024
#define C     512
#define NP    64
#define HEADS 16
#define INTER 256

// ---------------- scratch (__device__ globals, allocation-free) ----------------
//  ctxp/qp : per n [64 tok][256 chp] u32, bf16 pair along channel (lo = even ch)
//  thp/php : per n [128 chp][64 tok] u32, pair along channel (attn S-stage layout)
//  gp2     : per n [32 tokp][256 ch] u32, pair along token (attn AV layout)
//  yp      : per n [64 tok][128 chp] u32, pair along channel (out-proj B layout)
__device__ unsigned g_ctxp[(size_t)NB * 64 * 256];
__device__ unsigned g_qp[(size_t)NB * 64 * 256];
__device__ unsigned g_thp[(size_t)NB * 128 * 64];
__device__ unsigned g_php[(size_t)NB * 128 * 64];
__device__ unsigned g_gp2[(size_t)NB * 32 * 256];
__device__ unsigned g_yp[(size_t)NB * 64 * 128];
__device__ unsigned g_Wbf[262144];   // Wg,Wp,Wt,Wo (65536 u32 each)

// ---------------- helpers ----------------
__device__ __forceinline__ uint32_t smem_u32(const void* p) {
    uint32_t a;
    asm("{ .reg .u64 t; cvta.to.shared.u64 t, %1; cvt.u32.u64 %0, t; }" : "=r"(a) : "l"(p));
    return a;
}
__device__ __forceinline__ void cp_async16(void* dst, const void* src) {
    asm volatile("cp.async.cg.shared.global [%0], [%1], 16;"
                 :: "r"(smem_u32(dst)), "l"(src));
}
#define CP_COMMIT() asm volatile("cp.async.commit_group;" ::: "memory")
#define CP_WAIT(n)  asm volatile("cp.async.wait_group %0;" :: "n"(n) : "memory")

__device__ __forceinline__ uint32_t f2tf32(float f) {
    uint32_t r;
    asm("cvt.rna.tf32.f32 %0, %1;" : "=r"(r) : "f"(f));
    return r;
}
__device__ __forceinline__ uint32_t packbf(float lo, float hi) {
    uint32_t r;
    asm("cvt.rn.bf16x2.f32 %0, %1, %2;" : "=r"(r) : "f"(hi), "f"(lo));
    return r;
}
__device__ __forceinline__ void mma_tf32(float c[4], const uint32_t a[4], uint32_t b0, uint32_t b1) {
    asm volatile(
        "mma.sync.aligned.m16n8k8.row.col.f32.tf32.tf32.f32 "
        "{%0,%1,%2,%3}, {%4,%5,%6,%7}, {%8,%9}, {%0,%1,%2,%3};"
        : "+f"(c[0]), "+f"(c[1]), "+f"(c[2]), "+f"(c[3])
        : "r"(a[0]), "r"(a[1]), "r"(a[2]), "r"(a[3]), "r"(b0), "r"(b1));
}
__device__ __forceinline__ void mma_bf16(float c[4], const uint32_t a[4], uint32_t b0, uint32_t b1) {
    asm volatile(
        "mma.sync.aligned.m16n8k16.row.col.f32.bf16.bf16.f32 "
        "{%0,%1,%2,%3}, {%4,%5,%6,%7}, {%8,%9}, {%0,%1,%2,%3};"
        : "+f"(c[0]), "+f"(c[1]), "+f"(c[2]), "+f"(c[3])
        : "r"(a[0]), "r"(a[1]), "r"(a[2]), "r"(a[3]), "r"(b0), "r"(b1));
}
__device__ __forceinline__ void ldsm_x4(uint32_t& r0, uint32_t& r1, uint32_t& r2, uint32_t& r3,
                                        uint32_t addr) {
    asm volatile("ldmatrix.sync.aligned.m8n8.x4.shared.b16 {%0,%1,%2,%3}, [%4];"
                 : "=r"(r0), "=r"(r1), "=r"(r2), "=r"(r3) : "r"(addr));
}

// ---------------- K0: pack weights to bf16 pairs (k-contiguous) ----------------
__global__ __launch_bounds__(256)
void round_w(const float* __restrict__ Wg, const float* __restrict__ Wp,
             const float* __restrict__ Wt, const float* __restrict__ Wo,
             unsigned* __restrict__ dst)
{
    int i = blockIdx.x * 256 + threadIdx.x;   // 65536 pairs per matrix
    dst[i]              = packbf(Wg[2 * i], Wg[2 * i + 1]);
    dst[65536 + i]      = packbf(Wp[2 * i], Wp[2 * i + 1]);
    dst[131072 + i]     = packbf(Wt[2 * i], Wt[2 * i + 1]);
    dst[196608 + i]     = packbf(Wo[2 * i], Wo[2 * i + 1]);
}

// ============================================================================
// K1: position mixing via tf32 mma -> ctxp [tok][chp]; also transposes/packs
// query -> qp [tok][chp] through smem.
// ============================================================================
#define MSTR 68
__global__ __launch_bounds__(256, 2)
void mix_mma(const float* __restrict__ ctx, const float* __restrict__ Wm,
             const float* __restrict__ bm, const float* __restrict__ query,
             unsigned* __restrict__ ctxp, unsigned* __restrict__ qp)
{
    const int h = blockIdx.x;
    const int n0 = blockIdx.y * 4;

    extern __shared__ unsigned smem_u[];
    float* sm = (float*)smem_u;
    float* sA = sm;               // [128][MSTR]
    float* sB = sm + 128 * MSTR;  // [64][MSTR] (4352 floats)

    const int t = threadIdx.x;
    const int w = t >> 5, lane = t & 31;
    const int g = lane >> 2, tq = lane & 3;
    const int wm = w & 3, wn = w >> 2;

    #pragma unroll
    for (int i = 0; i < 8; i++) {
        int idx = t + 256 * i;
        int r = idx >> 4, c = idx & 15;
        const float* src = ctx + (((size_t)(n0 + (r >> 5)) * C) + h * 32 + (r & 31)) * NP + c * 4;
        cp_async16(sA + r * MSTR + c * 4, src);
    }
    #pragma unroll
    for (int i = 0; i < 4; i++) {
        int idx = t + 256 * i;
        int r = idx >> 4, c = idx & 15;
        cp_async16(sB + r * MSTR + c * 4, Wm + (size_t)h * 4096 + r * 64 + c * 4);
    }
    CP_COMMIT();
    CP_WAIT(0);
    __syncthreads();

    float acc[2][4][4];
    #pragma unroll
    for (int mt = 0; mt < 2; mt++)
        #pragma unroll
        for (int nt = 0; nt < 4; nt++)
            #pragma unroll
            for (int i = 0; i < 4; i++) acc[mt][nt][i] = 0.f;

    #pragma unroll
    for (int s = 0; s < 8; s++) {
        const int kb = s * 8;
        uint32_t af[2][4];
        #pragma unroll
        for (int mt = 0; mt < 2; mt++) {
            const int rb = wm * 32 + mt * 16;
            af[mt][0] = f2tf32(sA[(rb + g)     * MSTR + kb + tq]);
            af[mt][1] = f2tf32(sA[(rb + g + 8) * MSTR + kb + tq]);
            af[mt][2] = f2tf32(sA[(rb + g)     * MSTR + kb + tq + 4]);
            af[mt][3] = f2tf32(sA[(rb + g + 8) * MSTR + kb + tq + 4]);
        }
        uint32_t bf[4][2];
        #pragma unroll
        for (int nt = 0; nt < 4; nt++) {
            const int nb = wn * 32 + nt * 8;
            bf[nt][0] = f2tf32(sB[(nb + g) * MSTR + kb + tq]);
            bf[nt][1] = f2tf32(sB[(nb + g) * MSTR + kb + tq + 4]);
        }
        #pragma unroll
        for (int mt = 0; mt < 2; mt++)
            #pragma unroll
            for (int nt = 0; nt < 4; nt++)
                mma_tf32(acc[mt][nt], af[mt], bf[nt][0], bf[nt][1]);
    }
    __syncthreads();

    // epilogue: +ctx +bm, channel-pair pack, stage token-major [256 row][17]
    unsigned* sOut = (unsigned*)sB;   // 256*17 = 4352 u32 (exactly sB)
    #pragma unroll
    for (int mt = 0; mt < 2; mt++) {
        const int rl0 = wm * 32 + mt * 16 + g;
        const int rl1 = rl0 + 8;
        #pragma unroll
        for (int nt = 0; nt < 4; nt++) {
            const int col = wn * 32 + nt * 8 + tq * 2;
            const float b0 = __ldg(bm + h * 64 + col);
            const float b1 = __ldg(bm + h * 64 + col + 1);
            float v00 = acc[mt][nt][0] + sA[rl0 * MSTR + col]     + b0;
            float v01 = acc[mt][nt][1] + sA[rl0 * MSTR + col + 1] + b1;
            float v10 = acc[mt][nt][2] + sA[rl1 * MSTR + col]     + b0;
            float v11 = acc[mt][nt][3] + sA[rl1 * MSTR + col + 1] + b1;
            float n00 = __shfl_down_sync(0xffffffffu, v00, 4);
            float n01 = __shfl_down_sync(0xffffffffu, v01, 4);
            float n10 = __shfl_down_sync(0xffffffffu, v10, 4);
            float n11 = __shfl_down_sync(0xffffffffu, v11, 4);
            if (!(g & 1)) {
                const int cpl0 = mt * 8 + (g >> 1);     // d-pair (mt*16+g)/2
                const int cpl1 = cpl0 + 4;              // +8 d
                const int rowb = wm * 64 + col;         // nl*64 + tok
                sOut[(rowb)     * 17 + cpl0] = packbf(v00, n00);
                sOut[(rowb + 1) * 17 + cpl0] = packbf(v01, n01);
                sOut[(rowb)     * 17 + cpl1] = packbf(v10, n10);
                sOut[(rowb + 1) * 17 + cpl1] = packbf(v11, n11);
            }
        }
    }
    __syncthreads();
    #pragma unroll
    for (int i = 0; i < 16; i++) {
        int idx = t + 256 * i;              // < 4096
        int cpl = idx & 15, row = idx >> 4; // row = nl*64 + tok
        int nl = row >> 6, tok = row & 63;
        ctxp[((size_t)(n0 + nl) * 64 + tok) * 256 + h * 16 + cpl] = sOut[row * 17 + cpl];
    }

    // ---- query transpose+pack -> qp [tok][chp] (reuse sA region) ----
    float* sQ = sm;   // [64][33] floats
    for (int nl = 0; nl < 4; nl++) {
        __syncthreads();
        #pragma unroll
        for (int i = 0; i < 8; i++) {
            int idx = t + 256 * i;          // 2048 = 32 ch x 64 tok
            int ch = idx >> 6, tok = idx & 63;
            sQ[tok * 33 + ch] = query[(((size_t)(n0 + nl)) * C + h * 32 + ch) * NP + tok];
        }
        __syncthreads();
        #pragma unroll
        for (int i = 0; i < 4; i++) {
            int idx = t + 256 * i;          // 1024 = 64 tok x 16 cpl
            int tok = idx >> 4, cpl = idx & 15;
            qp[(((size_t)(n0 + nl)) * 64 + tok) * 256 + h * 16 + cpl] =
                packbf(sQ[tok * 33 + 2 * cpl], sQ[tok * 33 + 2 * cpl + 1]);
        }
    }
}

// ============================================================================
// bf16 GEMM core, 4-stage cp.async pipeline, ldmatrix for BOTH A and B frags.
// A: [128 Wrow][16 kp] stride 20;  B: [128 tok][16 kp] stride 20 (token-major).
// X0 = base of 128 contiguous token rows with row stride K/2 u32.
// EPI: 0 = [chp][tok] packed out, 1 = gp2 [tokp][ch], 2 = fp32+bias+resid
// ============================================================================
#define ASZ  2560            // 128 x 20 u32
#define BSZ  2560            // 128 x 20 u32
#define STG  (ASZ + BSZ)
template<int K, int EPI>
__device__ __forceinline__ void gemm_bf16_core(
    const unsigned* __restrict__ W, const unsigned* __restrict__ X0,
    const float* __restrict__ bias, const float* __restrict__ resid,
    float* __restrict__ Yf, unsigned* __restrict__ Yu,
    int rowoff, int n0, unsigned* smb, int t)
{
    constexpr int NIT = K / 32;

    const int w = t >> 5, lane = t & 31;
    const int g = lane >> 2, tq = lane & 3;
    const int wm = w & 3, wn = w >> 2;

    const uint32_t smb_addr = smem_u32(smb);
    const uint32_t arow = (uint32_t)(wm * 32 + (lane & 15)) * 80 + (uint32_t)(lane >> 4) * 16;
    const uint32_t brow = (uint32_t)(wn * 64 + (lane & 15)) * 80 + (uint32_t)(lane >> 4) * 16;

    float acc[2][8][4];
    #pragma unroll
    for (int mt = 0; mt < 2; mt++)
        #pragma unroll
        for (int nt = 0; nt < 8; nt++)
            #pragma unroll
            for (int i = 0; i < 4; i++) acc[mt][nt][i] = 0.f;

    auto copy_tiles = [&](int k0, int slot) {
        unsigned* dA = smb + slot * STG;
        unsigned* dB = dA + ASZ;
        #pragma unroll
        for (int i = 0; i < 2; i++) {               // A: 128 rows x 16 u32
            int idx = t + 256 * i;
            int r = idx >> 2, c4 = idx & 3;
            cp_async16(dA + r * 20 + c4 * 4, W + (size_t)r * (K / 2) + (k0 >> 1) + c4 * 4);
        }
        #pragma unroll
        for (int i = 0; i < 2; i++) {               // B: 128 tok rows x 16 u32
            int idx = t + 256 * i;
            int r = idx >> 2, c4 = idx & 3;
            cp_async16(dB + r * 20 + c4 * 4, X0 + (size_t)r * (K / 2) + (k0 >> 1) + c4 * 4);
        }
    };

    copy_tiles(0, 0);  CP_COMMIT();
    copy_tiles(32, 1); CP_COMMIT();
    copy_tiles(64, 2); CP_COMMIT();

    for (int it = 0; it < NIT; ++it) {
        if (it < NIT - 1) { CP_WAIT(2); } else { CP_WAIT(0); }
        __syncthreads();
        if (it + 3 < NIT) {
            copy_tiles((it + 3) * 32, (it + 3) & 3);
            CP_COMMIT();
        }

        const uint32_t sbase = smb_addr + (uint32_t)(it & 3) * (STG * 4);
        const uint32_t cAaddr = sbase + arow;
        const uint32_t cBaddr = sbase + ASZ * 4 + brow;
        #pragma unroll
        for (int j = 0; j < 2; j++) {
            uint32_t af[2][4];
            ldsm_x4(af[0][0], af[0][1], af[0][2], af[0][3], cAaddr + j * 32);
            ldsm_x4(af[1][0], af[1][1], af[1][2], af[1][3], cAaddr + 1280 + j * 32);
            uint32_t bf[8][2];
            #pragma unroll
            for (int p = 0; p < 4; p++) {
                uint32_t r0, r1, r2, r3;
                ldsm_x4(r0, r1, r2, r3, cBaddr + p * 1280 + j * 32);
                bf[2 * p][0] = r0; bf[2 * p][1] = r2;
                bf[2 * p + 1][0] = r1; bf[2 * p + 1][1] = r3;
            }
            #pragma unroll
            for (int mt = 0; mt < 2; mt++)
                #pragma unroll
                for (int nt = 0; nt < 8; nt++)
                    mma_bf16(acc[mt][nt], af[mt], bf[nt][0], bf[nt][1]);
        }
    }
    __syncthreads();

    if (EPI == 2) {
        #pragma unroll
        for (int mt = 0; mt < 2; mt++) {
            const int rl0 = wm * 32 + mt * 16 + g;
            const int rl1 = rl0 + 8;
            const float bv0 = bias[rl0];
            const float bv1 = bias[rl1];
            #pragma unroll
            for (int nt = 0; nt < 8; nt++) {
                const int gcol = wn * 64 + nt * 8 + tq * 2;
                const int n = n0 + (gcol >> 6);
                const int col = gcol & 63;
                size_t off0 = ((size_t)n * 512 + rowoff + rl0) * 64 + col;
                size_t off1 = ((size_t)n * 512 + rowoff + rl1) * 64 + col;
                float2 v0, v1;
                v0.x = acc[mt][nt][0] + bv0; v0.y = acc[mt][nt][1] + bv0;
                v1.x = acc[mt][nt][2] + bv1; v1.y = acc[mt][nt][3] + bv1;
                const float2 r0 = *(const float2*)(resid + off0);
                const float2 r1 = *(const float2*)(resid + off1);
                v0.x += r0.x; v0.y += r0.y;
                v1.x += r1.x; v1.y += r1.y;
                *(float2*)(Yf + off0) = v0;
                *(float2*)(Yf + off1) = v1;
            }
        }
    } else if (EPI == 1) {
        #pragma unroll
        for (int mt = 0; mt < 2; mt++) {
            const int rl0 = wm * 32 + mt * 16 + g;
            const int rl1 = rl0 + 8;
            const float bv0 = bias[rl0];
            const float bv1 = bias[rl1];
            #pragma unroll
            for (int nt = 0; nt < 8; nt++) {
                const int gcol = wn * 64 + nt * 8 + tq * 2;
                const int n = n0 + (gcol >> 6);
                const int colp = (gcol & 63) >> 1;
                size_t base = (size_t)n * 8192 + (size_t)colp * 256 + rowoff;
                Yu[base + rl0] = packbf(acc[mt][nt][0] + bv0, acc[mt][nt][1] + bv0);
                Yu[base + rl1] = packbf(acc[mt][nt][2] + bv1, acc[mt][nt][3] + bv1);
            }
        }
    } else {
        unsigned* sOut = smb;   // [64 chp][129]
        #pragma unroll
        for (int mt = 0; mt < 2; mt++) {
            const int rl0 = wm * 32 + mt * 16 + g;
            const int rl1 = rl0 + 8;
            const float bv0 = bias[rl0];
            const float bv1 = bias[rl1];
            #pragma unroll
            for (int nt = 0; nt < 8; nt++) {
                const int gcol = wn * 64 + nt * 8 + tq * 2;
                float v00 = acc[mt][nt][0] + bv0;
                float v01 = acc[mt][nt][1] + bv0;
                float v10 = acc[mt][nt][2] + bv1;
                float v11 = acc[mt][nt][3] + bv1;
                float n00 = __shfl_down_sync(0xffffffffu, v00, 4);
                float n01 = __shfl_down_sync(0xffffffffu, v01, 4);
                float n10 = __shfl_down_sync(0xffffffffu, v10, 4);
                float n11 = __shfl_down_sync(0xffffffffu, v11, 4);
                if (!(g & 1)) {
                    const int r0 = rl0 >> 1, r1 = rl1 >> 1;
                    sOut[r0 * 129 + gcol]     = packbf(v00, n00);
                    sOut[r0 * 129 + gcol + 1] = packbf(v01, n01);
                    sOut[r1 * 129 + gcol]     = packbf(v10, n10);
                    sOut[r1 * 129 + gcol + 1] = packbf(v11, n11);
                }
            }
        }
        __syncthreads();
        #pragma unroll
        for (int i = 0; i < 32; i++) {
            int idx = t + 256 * i;
            int chp = idx >> 7, c = idx & 127;
            int n = n0 + (c >> 6), tok = c & 63;
            Yu[((size_t)n * 128 + (rowoff >> 1) + chp) * 64 + tok] = sOut[chp * 129 + c];
        }
    }
}

// ---- merged projections: tiles 0-1 g (EPI1), 2-3 phi (EPI0), 4-5 theta (EPI0) ----
__global__ __launch_bounds__(256, 2)
void proj_mma(const unsigned* __restrict__ Wgb, const unsigned* __restrict__ Wpb,
              const unsigned* __restrict__ Wtb,
              const float* __restrict__ bg, const float* __restrict__ bp,
              const float* __restrict__ bt,
              const unsigned* __restrict__ ctxp, const unsigned* __restrict__ qp,
              unsigned* __restrict__ gp2, unsigned* __restrict__ php,
              unsigned* __restrict__ thp)
{
    extern __shared__ unsigned smem_u[];
    const int t = threadIdx.x;
    const int tile = blockIdx.x;
    const int n0 = blockIdx.y * 2;
    const int rowoff = (tile & 1) * 128;

    if (tile < 2) {
        gemm_bf16_core<512, 1>(Wgb + (size_t)rowoff * 256, ctxp + (size_t)n0 * 16384,
                               bg + rowoff, nullptr, nullptr, gp2, rowoff, n0, smem_u, t);
    } else if (tile < 4) {
        gemm_bf16_core<512, 0>(Wpb + (size_t)rowoff * 256, ctxp + (size_t)n0 * 16384,
                               bp + rowoff, nullptr, nullptr, php, rowoff, n0, smem_u, t);
    } else {
        gemm_bf16_core<512, 0>(Wtb + (size_t)rowoff * 256, qp + (size_t)n0 * 16384,
                               bt + rowoff, nullptr, nullptr, thp, rowoff, n0, smem_u, t);
    }
}

// ---- output projection ----
__global__ __launch_bounds__(256, 2)
void out_mma(const unsigned* __restrict__ Wob, const float* __restrict__ bo,
             const unsigned* __restrict__ yp, const float* __restrict__ query,
             float* __restrict__ out)
{
    extern __shared__ unsigned smem_u[];
    const int t = threadIdx.x;
    const int rowoff = blockIdx.x * 128;
    const int n0 = blockIdx.y * 2;
    gemm_bf16_core<256, 2>(Wob + (size_t)rowoff * 128, yp + (size_t)n0 * 8192,
                           bo + rowoff, query, out, nullptr, rowoff, n0, smem_u, t);
}

// ============================================================================
// attention, bf16 mma end-to-end; yp now written token-major [tok][chp]
// ============================================================================
#define AT  0
#define AP  1152
#define AG  2304
#define APP 3840
#define ATOT 8448   // u32

__global__ __launch_bounds__(256, 3)
void attn_mma(const unsigned* __restrict__ thp, const unsigned* __restrict__ php,
              const unsigned* __restrict__ gp2, unsigned* __restrict__ yp)
{
    extern __shared__ unsigned smem_u[];
    const int hp = blockIdx.x;
    const int n  = blockIdx.y;
    const int t = threadIdx.x;
    const int w = t >> 5, lane = t & 31;
    const int g = lane >> 2, tq = lane & 3;
    const int hl = w >> 2;
    const int rb = (w & 3) * 16;

    {
        int hd = t >> 7, dp = (t >> 4) & 7, c4 = t & 15;
        size_t srcTP = ((size_t)n * 128 + (2 * hp + hd) * 8 + dp) * 64 + c4 * 4;
        cp_async16(smem_u + AT + hd * 576 + dp * 72 + c4 * 4, thp + srcTP);
        cp_async16(smem_u + AP + hd * 576 + dp * 72 + c4 * 4, php + srcTP);
        int tokp = (t >> 2) & 31, c4g = t & 3;
        cp_async16(smem_u + AG + hd * 768 + tokp * 24 + c4g * 4,
                   gp2 + (size_t)n * 8192 + (size_t)tokp * 256 + (2 * hp + hd) * 16 + c4g * 4);
    }
    CP_COMMIT();
    CP_WAIT(0);
    __syncthreads();

    const unsigned* Tm = smem_u + AT + hl * 576;
    const unsigned* Pm = smem_u + AP + hl * 576;
    const unsigned* Gm = smem_u + AG + hl * 768;
    unsigned*       Pp = smem_u + APP + hl * 2304;

    float sacc[8][4];
    #pragma unroll
    for (int nt = 0; nt < 8; nt++)
        #pragma unroll
        for (int i = 0; i < 4; i++) sacc[nt][i] = 0.f;
    {
        uint32_t af[4];
        af[0] = Tm[tq * 72 + rb + g];
        af[1] = Tm[tq * 72 + rb + g + 8];
        af[2] = Tm[(tq + 4) * 72 + rb + g];
        af[3] = Tm[(tq + 4) * 72 + rb + g + 8];
        #pragma unroll
        for (int nt = 0; nt < 8; nt++) {
            uint32_t b0 = Pm[tq * 72 + nt * 8 + g];
            uint32_t b1 = Pm[(tq + 4) * 72 + nt * 8 + g];
            mma_bf16(sacc[nt], af, b0, b1);
        }
    }

    {
        float m0 = -1e30f, m1 = -1e30f;
        #pragma unroll
        for (int nt = 0; nt < 8; nt++) {
            #pragma unroll
            for (int i = 0; i < 4; i++) sacc[nt][i] *= 0.25f;
            m0 = fmaxf(m0, fmaxf(sacc[nt][0], sacc[nt][1]));
            m1 = fmaxf(m1, fmaxf(sacc[nt][2], sacc[nt][3]));
        }
        m0 = fmaxf(m0, __shfl_xor_sync(0xffffffffu, m0, 1));
        m0 = fmaxf(m0, __shfl_xor_sync(0xffffffffu, m0, 2));
        m1 = fmaxf(m1, __shfl_xor_sync(0xffffffffu, m1, 1));
        m1 = fmaxf(m1, __shfl_xor_sync(0xffffffffu, m1, 2));
        float s0 = 0.f, s1 = 0.f;
        #pragma unroll
        for (int nt = 0; nt < 8; nt++) {
            sacc[nt][0] = __expf(sacc[nt][0] - m0);
            sacc[nt][1] = __expf(sacc[nt][1] - m0);
            sacc[nt][2] = __expf(sacc[nt][2] - m1);
            sacc[nt][3] = __expf(sacc[nt][3] - m1);
            s0 += sacc[nt][0] + sacc[nt][1];
            s1 += sacc[nt][2] + sacc[nt][3];
        }
        s0 += __shfl_xor_sync(0xffffffffu, s0, 1);
        s0 += __shfl_xor_sync(0xffffffffu, s0, 2);
        s1 += __shfl_xor_sync(0xffffffffu, s1, 1);
        s1 += __shfl_xor_sync(0xffffffffu, s1, 2);
        const float i0 = 1.0f / s0, i1 = 1.0f / s1;
        #pragma unroll
        for (int nt = 0; nt < 8; nt++) {
            Pp[(rb + g)     * 36 + nt * 4 + tq] = packbf(sacc[nt][0] * i0, sacc[nt][1] * i0);
            Pp[(rb + g + 8) * 36 + nt * 4 + tq] = packbf(sacc[nt][2] * i1, sacc[nt][3] * i1);
        }
    }
    __syncwarp();

    float acc2[2][4];
    #pragma unroll
    for (int nt = 0; nt < 2; nt++)
        #pragma unroll
        for (int i = 0; i < 4; i++) acc2[nt][i] = 0.f;

    #pragma unroll
    for (int j = 0; j < 4; j++) {
        uint32_t pa[4];
        pa[0] = Pp[(rb + g)     * 36 + j * 8 + tq];
        pa[1] = Pp[(rb + g + 8) * 36 + j * 8 + tq];
        pa[2] = Pp[(rb + g)     * 36 + j * 8 + tq + 4];
        pa[3] = Pp[(rb + g + 8) * 36 + j * 8 + tq + 4];
        #pragma unroll
        for (int nt = 0; nt < 2; nt++) {
            uint32_t b0 = Gm[(j * 8 + tq)     * 24 + nt * 8 + g];
            uint32_t b1 = Gm[(j * 8 + tq + 4) * 24 + nt * 8 + g];
            mma_bf16(acc2[nt], pa, b0, b1);
        }
    }

    // yp token-major: yp[(n*64+tok)*128 + chp]
    const int hgl = 2 * hp + hl;
    #pragma unroll
    for (int nt = 0; nt < 2; nt++) {
        const int chp = hgl * 8 + nt * 4 + tq;
        yp[((size_t)n * 64 + rb + g)     * 128 + chp] = packbf(acc2[nt][0], acc2[nt][1]);
        yp[((size_t)n * 64 + rb + g + 8) * 128 + chp] = packbf(acc2[nt][2], acc2[nt][3]);
    }
}

// ---------------- launch ----------------
extern "C" void kernel_launch(void* const* d_in, const int* in_sizes, int n_in,
                              void* d_out, int out_size)
{
    const float* query   = (const float*)d_in[0];
    const float* context = (const float*)d_in[1];
    const float* Wm = (const float*)d_in[2];
    const float* bm = (const float*)d_in[3];
    const float* Wg = (const float*)d_in[4];
    const float* bg = (const float*)d_in[5];
    const float* Wt = (const float*)d_in[6];
    const float* bt = (const float*)d_in[7];
    const float* Wp = (const float*)d_in[8];
    const float* bp = (const float*)d_in[9];
    const float* Wo = (const float*)d_in[10];
    const float* bo = (const float*)d_in[11];
    float* out = (float*)d_out;

    unsigned *ctxp, *qp, *thp, *php, *gp2, *yp, *wr;
    cudaGetSymbolAddress((void**)&ctxp, g_ctxp);
    cudaGetSymbolAddress((void**)&qp,   g_qp);
    cudaGetSymbolAddress((void**)&thp,  g_thp);
    cudaGetSymbolAddress((void**)&php,  g_php);
    cudaGetSymbolAddress((void**)&gp2,  g_gp2);
    cudaGetSymbolAddress((void**)&yp,   g_yp);
    cudaGetSymbolAddress((void**)&wr,   g_Wbf);

    const unsigned* Wgb = wr;
    const unsigned* Wpb = wr + 65536;
    const unsigned* Wtb = wr + 131072;
    const unsigned* Wob = wr + 196608;

    const int GSMEM = 4 * STG * 4;                        // 81920 B
    const int XSMEM = (128 * MSTR + 64 * MSTR) * 4;       // 52224 B
    const int ASMEM = ATOT * 4;                           // 33792 B
    cudaFuncSetAttribute((const void*)proj_mma,
                         cudaFuncAttributeMaxDynamicSharedMemorySize, GSMEM);
    cudaFuncSetAttribute((const void*)out_mma,
                         cudaFuncAttributeMaxDynamicSharedMemorySize, GSMEM);
    cudaFuncSetAttribute((const void*)mix_mma,
                         cudaFuncAttributeMaxDynamicSharedMemorySize, XSMEM);
    cudaFuncSetAttribute((const void*)attn_mma,
                         cudaFuncAttributeMaxDynamicSharedMemorySize, ASMEM);

    // 0) pack weights to bf16
    round_w<<<256, 256>>>(Wg, Wp, Wt, Wo, wr);

    // 1) position mixing -> ctxp [tok][chp]; query transpose/pack -> qp
    mix_mma<<<dim3(HEADS, NB / 4), 256, XSMEM>>>(context, Wm, bm, query, ctxp, qp);

    // 2) merged projections (ldmatrix A+B, 4-stage)
    proj_mma<<<dim3(6, NB / 2), 256, GSMEM>>>(
        Wgb, Wpb, Wtb, bg, bp, bt, ctxp, qp, gp2, php, thp);

    // 3) attention (bf16 mma end-to-end)
    attn_mma<<<dim3(HEADS / 2, NB), 256, ASMEM>>>(thp, php, gp2, yp);

    // 4) output projection + bias + residual (fp32 epilogue)
    out_mma<<<dim3(4, NB / 2), 256, GSMEM>>>(Wob, bo, yp, query, out);
}